// round 5
// baseline (speedup 1.0000x reference)
#include <cuda_runtime.h>

// ---------------------------------------------------------------------------
// Pose2Mesh fully-collapsed linear implementation.
// All heads + neighbor 3x3 contractions + root subtraction folded into one
// dense W'(57 x 151) + b'(151); main kernel = out(B,151) = x(B,57) @ W' + b'
// using packed fma.rn.f32x2 (FFMA2).
// ---------------------------------------------------------------------------

#define D_DIM   2048
#define NC      57      // J*3
#define NK      151
#define NKPAD   160
#define KSPLIT  128
#define KCHUNK  16      // D_DIM / KSPLIT
#define H_DIM   512
#define CPB     32      // cols per block (main)
#define NSLICES 5       // 160/32
#define RPB     32      // rows per block (main)
#define TPB     64      // threads per block (main)

// scratch (allocation-free: __device__ globals)
__device__ float g_M1[24 * 9];
__device__ float g_M2[24 * 9];
__device__ float g_bp1[72];
__device__ float g_bp2[72];
__device__ float g_Wpart[KSPLIT * 58 * NKPAD];
__device__ float g_W[NC * NKPAD];
__device__ float g_b[NKPAD];

// NEB1[j]*3 and NEB2[j]*3 (base offsets into the 57-float joint vector)
__constant__ int c_NB1[24] = {51,33,36,51,39,42,51,45,48,54,45,48,54,54,54,54,15,18,21,24,27,30,27,30};
__constant__ int c_NB2[24] = {54,51,51,54,33,36,54,39,42,51,39,42, 0,15,18, 0,54,54,15,18,21,24,21,24};

// ---------------------------------------------------------------------------
// Kernel A (fused): blocks [0, 5*KSPLIT) = fold GEMM split-K partials,
//                   blocks [5*KSPLIT, +72) = per-joint 3x3 M1/M2 + bias dots
// ---------------------------------------------------------------------------
__device__ __forceinline__ float fetchB(int f, int col,
                                        const float* __restrict__ Wsh, const float* __restrict__ Wca,
                                        const float* __restrict__ Wph, const float* __restrict__ Wlf,
                                        const float* __restrict__ Rf)
{
    if (col < 10)  return Wsh[f * 10 + col];
    if (col < 13)  return Wca[f * 3  + (col - 10)];
    if (col < 59)  return Wph[f * 46 + (col - 13)];
    if (col < 79)  return Wlf[f * 20 + (col - 59)];
    int t = col - 79;
    int j = t / 3, o = t - j * 3;
    return Rf[(j * D_DIM + f) * 3 + o];
}

__global__ void __launch_bounds__(256)
precompute_kernel(const float* __restrict__ W_enc, const float* __restrict__ b_enc,
                  const float* __restrict__ W_shape, const float* __restrict__ W_cam,
                  const float* __restrict__ W_phi,   const float* __restrict__ W_leaf,
                  const float* __restrict__ Rf,
                  const float* __restrict__ L1_w, const float* __restrict__ L1_b,
                  const float* __restrict__ L2_w, const float* __restrict__ L2_b,
                  const float* __restrict__ R1,   const float* __restrict__ R2)
{
    int bx  = blockIdx.x;
    int tid = threadIdx.x;

    if (bx >= 5 * KSPLIT) {
        // ---- compute_M: 72 blocks x 8 warps; one warp per (j, t) dot of len 512
        int mb   = bx - 5 * KSPLIT;       // 0..71
        int j    = mb % 24;
        int g    = mb / 24;               // 0..2
        int lane = tid & 31;
        int t    = g * 8 + (tid >> 5);    // 0..23

        const float* ap;
        const float* rp;
        if (t < 9) {
            int c = t / 3, o = t % 3;
            ap = L1_w + (j * 3 + c) * H_DIM;
            rp = R1 + j * H_DIM * 3 + o;
        } else if (t < 18) {
            int tt = t - 9; int c = tt / 3, o = tt % 3;
            ap = L2_w + (j * 3 + c) * H_DIM;
            rp = R2 + j * H_DIM * 3 + o;
        } else if (t < 21) {
            int o = t - 18;
            ap = L1_b + j * H_DIM;
            rp = R1 + j * H_DIM * 3 + o;
        } else {
            int o = t - 21;
            ap = L2_b + j * H_DIM;
            rp = R2 + j * H_DIM * 3 + o;
        }
        // batched loads: full unroll (constant trip), all 32 LDGs in flight
        float av[16], rv[16];
        #pragma unroll
        for (int i = 0; i < 16; i++) {
            int h = lane + 32 * i;
            av[i] = ap[h];
            rv[i] = rp[h * 3];
        }
        float sum = 0.f;
        #pragma unroll
        for (int i = 0; i < 16; i++) sum = fmaf(av[i], rv[i], sum);
        #pragma unroll
        for (int d = 16; d > 0; d >>= 1) sum += __shfl_xor_sync(0xffffffffu, sum, d);
        if (lane == 0) {
            if      (t < 9)  g_M1[j * 9 + t]          = sum;
            else if (t < 18) g_M2[j * 9 + (t - 9)]    = sum;
            else if (t < 21) g_bp1[j * 3 + (t - 18)]  = sum;
            else             g_bp2[j * 3 + (t - 21)]  = sum;
        }
        return;
    }

    // ---- fold GEMM: K=16 chunk per block, split-K partials
    __shared__ float As[64][KCHUNK + 1];
    __shared__ __align__(16) float Bs[KCHUNK][36];

    int ct = bx % 5;              // column tile (5 tiles of 32 -> 160)
    int ks = bx / 5;              // k-split index (0..127)
    int kbase = ks * KCHUNK;

    // batched A loads (58*16 = 928 elems, 256 thr -> 4 slots each, guarded)
    float va[4];
    int   vr[4], vk[4];
    #pragma unroll
    for (int i = 0; i < 4; i++) {
        int idx = tid + 256 * i;
        int r = idx >> 4, kk = idx & 15;
        vr[i] = r; vk[i] = kk;
        float v = 0.f;
        if (r < NC)       v = W_enc[r * D_DIM + kbase + kk];
        else if (r == NC) v = b_enc[kbase + kk];
        va[i] = v;
    }
    // batched B loads (16*32 = 512 / 256 = 2 each)
    float vb[2];
    #pragma unroll
    for (int i = 0; i < 2; i++) {
        int idx = tid + 256 * i;
        int kk = idx >> 5, cl = idx & 31;
        int gcol = ct * 32 + cl;
        vb[i] = (gcol < NK) ? fetchB(kbase + kk, gcol, W_shape, W_cam, W_phi, W_leaf, Rf) : 0.f;
    }
    #pragma unroll
    for (int i = 0; i < 4; i++)
        if (vr[i] < 64) As[vr[i]][vk[i]] = va[i];
    #pragma unroll
    for (int i = 0; i < 2; i++) {
        int idx = tid + 256 * i;
        Bs[idx >> 5][idx & 31] = vb[i];
    }
    __syncthreads();

    // compute: thread = (row r, col group cg of 8)
    int r  = tid >> 2;            // 0..63
    int cg = tid & 3;             // 0..3
    float acc[8];
    #pragma unroll
    for (int e = 0; e < 8; e++) acc[e] = 0.f;
    #pragma unroll
    for (int kk = 0; kk < KCHUNK; kk++) {
        float  xc = As[r][kk];
        float4 w0 = *(const float4*)&Bs[kk][cg * 8];
        float4 w1 = *(const float4*)&Bs[kk][cg * 8 + 4];
        acc[0] = fmaf(xc, w0.x, acc[0]); acc[1] = fmaf(xc, w0.y, acc[1]);
        acc[2] = fmaf(xc, w0.z, acc[2]); acc[3] = fmaf(xc, w0.w, acc[3]);
        acc[4] = fmaf(xc, w1.x, acc[4]); acc[5] = fmaf(xc, w1.y, acc[5]);
        acc[6] = fmaf(xc, w1.z, acc[6]); acc[7] = fmaf(xc, w1.w, acc[7]);
    }
    if (r < 58) {
        float* dst = &g_Wpart[(ks * 58 + r) * NKPAD + ct * 32 + cg * 8];
        *(float4*)dst       = make_float4(acc[0], acc[1], acc[2], acc[3]);
        *(float4*)(dst + 4) = make_float4(acc[4], acc[5], acc[6], acc[7]);
    }
}

// ---------------------------------------------------------------------------
// Kernel B: reduce split-K partials, fold neighbor 3x3 terms AND the root
// (joint 0) subtraction directly into W' and b'. Pads cols [151,160) to 0.
// ---------------------------------------------------------------------------
__global__ void __launch_bounds__(NKPAD)
finalize_kernel(const float* __restrict__ b_shape, const float* __restrict__ b_cam,
                const float* __restrict__ b_phi,   const float* __restrict__ b_leaf,
                const float* __restrict__ init_shape, const float* __restrict__ init_cam,
                const float* __restrict__ reg_b)
{
    int row = blockIdx.x;    // 0..57
    int col = threadIdx.x;   // 0..159
    float s = 0.f;
    #pragma unroll
    for (int p = 0; p < KSPLIT; p++) s += g_Wpart[(p * 58 + row) * NKPAD + col];

    bool isPose = (col >= 79 && col < NK);
    int t = 0, j = 0, o = 0;
    float s0 = 0.f;
    if (isPose) {
        t = col - 79; j = t / 3; o = t - 3 * j;
        #pragma unroll
        for (int p = 0; p < KSPLIT; p++) s0 += g_Wpart[(p * 58 + row) * NKPAD + 79 + o];
    }

    if (row < NC) {
        float w;
        if (col >= NK) {
            w = 0.f;
        } else if (!isPose) {
            w = s;
        } else {
            w = s - s0;
            int a1 = c_NB1[j], a2 = c_NB2[j];
            if (row >= a1 && row < a1 + 3) w += g_M1[j * 9 + (row - a1) * 3 + o];
            if (row >= a2 && row < a2 + 3) w += g_M2[j * 9 + (row - a2) * 3 + o];
            // subtract joint-0 neighbor scatter (NB1[0]=51, NB2[0]=54)
            if (row >= 51 && row < 54) w -= g_M1[(row - 51) * 3 + o];
            if (row >= 54 && row < 57) w -= g_M2[(row - 54) * 3 + o];
        }
        g_W[row * NKPAD + col] = w;
    } else {
        float bv;
        if      (col >= NK) bv = 0.f;
        else if (col < 10)  bv = s + b_shape[col] + init_shape[col];
        else if (col < 13)  bv = s + b_cam[col - 10] + init_cam[col - 10];
        else if (col < 59)  bv = s + b_phi[col - 13];
        else if (col < 79)  bv = s + b_leaf[col - 59];
        else {
            float bt = s  + reg_b[t] + g_bp1[t] + g_bp2[t];
            float b0 = s0 + reg_b[o] + g_bp1[o] + g_bp2[o];
            bv = bt - b0;
        }
        g_b[col] = bv;
    }
}

// ---------------------------------------------------------------------------
// Kernel C: main — out(B,151) = x(B,57) @ W' + b'. FFMA2 (fma.rn.f32x2).
// Block = 64 threads covering 32 rows x 32 cols: thread = 2 rows x 8 cols.
// grid = (B/32, 5 slices) = 1280 blocks -> high occupancy.
// ---------------------------------------------------------------------------
__global__ void __launch_bounds__(TPB)
main_kernel(const float* __restrict__ joints, float* __restrict__ out, int B)
{
    __shared__ __align__(16) float Xs[RPB * NC];     // 32*57*4 = 7296 B
    __shared__ __align__(16) float Ws[NC][CPB];      // 57*32*4 = 7296 B
    __shared__ float bias_s[CPB];

    const int tid = threadIdx.x;
    const int rb  = blockIdx.x * RPB;
    const int k0  = blockIdx.y * CPB;

    // output section offsets (pose first, per output layout)
    const int CAM_OFF   = B * 72;
    const int PHI_OFF   = CAM_OFF + B * 3;
    const int LEAF_OFF  = PHI_OFF + B * 46;
    const int SHAPE_OFF = LEAF_OFF + B * 20;

    // ---- stage X (batched): 32*57 floats = 456 float4, 16B-aligned ----
    if (rb + RPB <= B) {
        const float4* jp = (const float4*)(joints + rb * NC);
        float4 xv[8];
        #pragma unroll
        for (int i = 0; i < 8; i++) {
            int idx = tid + TPB * i;
            if (idx < 456) xv[i] = jp[idx];
        }
        #pragma unroll
        for (int i = 0; i < 8; i++) {
            int idx = tid + TPB * i;
            if (idx < 456) ((float4*)Xs)[idx] = xv[i];
        }
    } else {
        int nr = B - rb;
        for (int idx = tid; idx < nr * NC; idx += TPB)
            Xs[idx] = joints[rb * NC + idx];
    }

    // ---- stage W slice (batched): 57 rows x 8 float4 = 456 float4 ----
    {
        float4 wv[8];
        #pragma unroll
        for (int i = 0; i < 8; i++) {
            int idx = tid + TPB * i;
            if (idx < 456) {
                int r = idx >> 3, q = idx & 7;
                wv[i] = *(const float4*)(g_W + r * NKPAD + k0 + q * 4);
            }
        }
        #pragma unroll
        for (int i = 0; i < 8; i++) {
            int idx = tid + TPB * i;
            if (idx < 456) {
                int r = idx >> 3, q = idx & 7;
                *(float4*)&Ws[r][q * 4] = wv[i];
            }
        }
    }
    if (tid < CPB) bias_s[tid] = g_b[k0 + tid];
    __syncthreads();

    const int ty = tid >> 2;          // 0..15 -> rows 2ty, 2ty+1
    const int cg = tid & 3;           // col group: cols cg*8 .. cg*8+7
    const int r0 = 2 * ty, r1 = r0 + 1;

    // accumulators: 2 rows x 4 f32x2 (8 outputs per row)
    unsigned long long accA[4], accB[4];
    #pragma unroll
    for (int e = 0; e < 4; e++) {
        float lo = bias_s[cg * 8 + 2 * e];
        float hi = bias_s[cg * 8 + 2 * e + 1];
        unsigned long long p;
        asm("mov.b64 %0, {%1, %2};" : "=l"(p) : "f"(lo), "f"(hi));
        accA[e] = p; accB[e] = p;
    }

    const float* x0 = &Xs[r0 * NC];
    const float* x1 = &Xs[r1 * NC];
    #pragma unroll
    for (int c = 0; c < NC; c++) {
        float a = x0[c], b = x1[c];
        unsigned long long xa, xb;
        asm("mov.b64 %0, {%1, %1};" : "=l"(xa) : "f"(a));
        asm("mov.b64 %0, {%1, %1};" : "=l"(xb) : "f"(b));
        const ulonglong2* wp = (const ulonglong2*)&Ws[c][cg * 8];
        ulonglong2 wv0 = wp[0];   // cols 0..3 as two f32x2
        ulonglong2 wv1 = wp[1];   // cols 4..7
        asm("fma.rn.f32x2 %0, %1, %2, %0;" : "+l"(accA[0]) : "l"(xa), "l"(wv0.x));
        asm("fma.rn.f32x2 %0, %1, %2, %0;" : "+l"(accA[1]) : "l"(xa), "l"(wv0.y));
        asm("fma.rn.f32x2 %0, %1, %2, %0;" : "+l"(accA[2]) : "l"(xa), "l"(wv1.x));
        asm("fma.rn.f32x2 %0, %1, %2, %0;" : "+l"(accA[3]) : "l"(xa), "l"(wv1.y));
        asm("fma.rn.f32x2 %0, %1, %2, %0;" : "+l"(accB[0]) : "l"(xb), "l"(wv0.x));
        asm("fma.rn.f32x2 %0, %1, %2, %0;" : "+l"(accB[1]) : "l"(xb), "l"(wv0.y));
        asm("fma.rn.f32x2 %0, %1, %2, %0;" : "+l"(accB[2]) : "l"(xb), "l"(wv1.x));
        asm("fma.rn.f32x2 %0, %1, %2, %0;" : "+l"(accB[3]) : "l"(xb), "l"(wv1.y));
    }

    // unpack + store (section-mapped), both rows
    #pragma unroll
    for (int rr = 0; rr < 2; rr++) {
        int b = rb + (rr == 0 ? r0 : r1);
        if (b >= B) continue;
        const unsigned long long* acc = (rr == 0) ? accA : accB;
        float v[8];
        #pragma unroll
        for (int e = 0; e < 4; e++) {
            float lo, hi;
            asm("mov.b64 {%0, %1}, %2;" : "=f"(lo), "=f"(hi) : "l"(acc[e]));
            v[2 * e] = lo; v[2 * e + 1] = hi;
        }
        #pragma unroll
        for (int e = 0; e < 8; e++) {
            int k = k0 + cg * 8 + e;
            if (k < NK) {
                float val = v[e];
                if      (k < 10) out[SHAPE_OFF + b * 10 + k]        = val;
                else if (k < 13) out[CAM_OFF   + b * 3  + (k - 10)] = val;
                else if (k < 59) out[PHI_OFF   + b * 46 + (k - 13)] = val;
                else if (k < 79) out[LEAF_OFF  + b * 20 + (k - 59)] = val;
                else             out[b * 72 + (k - 79)]             = val;
            }
        }
    }
}

// ---------------------------------------------------------------------------
extern "C" void kernel_launch(void* const* d_in, const int* in_sizes, int n_in,
                              void* d_out, int out_size)
{
    const float* joints     = (const float*)d_in[0];
    const float* W_enc      = (const float*)d_in[1];
    const float* b_enc      = (const float*)d_in[2];
    const float* W_shape    = (const float*)d_in[3];
    const float* b_shape    = (const float*)d_in[4];
    const float* W_cam      = (const float*)d_in[5];
    const float* b_cam      = (const float*)d_in[6];
    const float* W_phi      = (const float*)d_in[7];
    const float* b_phi      = (const float*)d_in[8];
    const float* W_leaf     = (const float*)d_in[9];
    const float* b_leaf     = (const float*)d_in[10];
    const float* init_shape = (const float*)d_in[11];
    const float* init_cam   = (const float*)d_in[12];
    const float* L1_w       = (const float*)d_in[13];
    const float* L1_b       = (const float*)d_in[14];
    const float* L2_w       = (const float*)d_in[15];
    const float* L2_b       = (const float*)d_in[16];
    const float* Rf         = (const float*)d_in[17];
    const float* R1         = (const float*)d_in[18];
    const float* R2         = (const float*)d_in[19];
    const float* reg_b      = (const float*)d_in[20];

    int B = in_sizes[0] / NC;

    precompute_kernel<<<5 * KSPLIT + 72, 256>>>(W_enc, b_enc, W_shape, W_cam, W_phi, W_leaf, Rf,
                                                L1_w, L1_b, L2_w, L2_b, R1, R2);
    finalize_kernel<<<58, NKPAD>>>(b_shape, b_cam, b_phi, b_leaf, init_shape, init_cam, reg_b);
    main_kernel<<<dim3((B + RPB - 1) / RPB, NSLICES), TPB>>>(joints, (float*)d_out, B);
}

// round 6
// speedup vs baseline: 1.0795x; 1.0795x over previous
#include <cuda_runtime.h>

// ---------------------------------------------------------------------------
// Pose2Mesh fully-collapsed linear implementation.
// All heads + neighbor 3x3 contractions + root subtraction folded into one
// dense W'(57 x 151) + b'(151); main kernel = out(B,151) = x(B,57) @ W' + b'.
// ---------------------------------------------------------------------------

#define D_DIM   2048
#define NC      57      // J*3
#define NK      151
#define NKPAD   160
#define KSPLIT  64
#define KCHUNK  32      // D_DIM / KSPLIT
#define H_DIM   512
#define CPB     16      // cols per block (main)
#define NSLICES 10      // 160/16
#define RPB     64      // rows per block (main)
#define TPB     128     // threads per block (main)

// scratch (allocation-free: __device__ globals)
__device__ float g_M1[24 * 9];
__device__ float g_M2[24 * 9];
__device__ float g_bp1[72];
__device__ float g_bp2[72];
__device__ float g_Wpart[KSPLIT * 58 * NKPAD];
__device__ float g_W[NC * NKPAD];
__device__ float g_b[NKPAD];

// NEB1[j]*3 and NEB2[j]*3 (base offsets into the 57-float joint vector)
__constant__ int c_NB1[24] = {51,33,36,51,39,42,51,45,48,54,45,48,54,54,54,54,15,18,21,24,27,30,27,30};
__constant__ int c_NB2[24] = {54,51,51,54,33,36,54,39,42,51,39,42, 0,15,18, 0,54,54,15,18,21,24,21,24};

// ---------------------------------------------------------------------------
// Kernel A (fused): blocks [0, 5*KSPLIT) = fold GEMM split-K partials,
//                   blocks [5*KSPLIT, +72) = per-joint 3x3 M1/M2 + bias dots
// ---------------------------------------------------------------------------
__device__ __forceinline__ float fetchB(int f, int col,
                                        const float* __restrict__ Wsh, const float* __restrict__ Wca,
                                        const float* __restrict__ Wph, const float* __restrict__ Wlf,
                                        const float* __restrict__ Rf)
{
    if (col < 10)  return Wsh[f * 10 + col];
    if (col < 13)  return Wca[f * 3  + (col - 10)];
    if (col < 59)  return Wph[f * 46 + (col - 13)];
    if (col < 79)  return Wlf[f * 20 + (col - 59)];
    int t = col - 79;
    int j = t / 3, o = t - j * 3;
    return Rf[(j * D_DIM + f) * 3 + o];
}

__global__ void __launch_bounds__(256)
precompute_kernel(const float* __restrict__ W_enc, const float* __restrict__ b_enc,
                  const float* __restrict__ W_shape, const float* __restrict__ W_cam,
                  const float* __restrict__ W_phi,   const float* __restrict__ W_leaf,
                  const float* __restrict__ Rf,
                  const float* __restrict__ L1_w, const float* __restrict__ L1_b,
                  const float* __restrict__ L2_w, const float* __restrict__ L2_b,
                  const float* __restrict__ R1,   const float* __restrict__ R2)
{
    int bx  = blockIdx.x;
    int tid = threadIdx.x;

    if (bx >= 5 * KSPLIT) {
        // ---- compute_M: 72 blocks x 8 warps; one warp per (j, t) dot of len 512
        int mb   = bx - 5 * KSPLIT;       // 0..71
        int j    = mb % 24;
        int g    = mb / 24;               // 0..2
        int lane = tid & 31;
        int t    = g * 8 + (tid >> 5);    // 0..23

        const float* ap;
        const float* rp;
        if (t < 9) {
            int c = t / 3, o = t % 3;
            ap = L1_w + (j * 3 + c) * H_DIM;
            rp = R1 + j * H_DIM * 3 + o;
        } else if (t < 18) {
            int tt = t - 9; int c = tt / 3, o = tt % 3;
            ap = L2_w + (j * 3 + c) * H_DIM;
            rp = R2 + j * H_DIM * 3 + o;
        } else if (t < 21) {
            int o = t - 18;
            ap = L1_b + j * H_DIM;
            rp = R1 + j * H_DIM * 3 + o;
        } else {
            int o = t - 21;
            ap = L2_b + j * H_DIM;
            rp = R2 + j * H_DIM * 3 + o;
        }
        // vectorized batched loads: thread handles h = lane*4 + 128*i, 4 elems each.
        // A: 1 float4; R (stride-3): 12 consecutive floats = 3 float4
        // (base (lane*4+128i)*3 floats -> 48B-aligned).
        float4 av[4];
        float4 rv[4][3];
        #pragma unroll
        for (int i = 0; i < 4; i++) {
            int h = lane * 4 + 128 * i;
            av[i] = *(const float4*)(ap + h);
            const float4* rp4 = (const float4*)(rp - ((t < 9) ? (t % 3) : (t < 18) ? ((t - 9) % 3) : (t < 21) ? (t - 18) : (t - 21)) + h * 3);
            // rp points at R + o; element h is rp[h*3] = R[h*3 + o].
            // load R[3h .. 3h+11] and pick +o lanes below.
            rv[i][0] = rp4[0];
            rv[i][1] = rp4[1];
            rv[i][2] = rp4[2];
        }
        int o = (t < 9) ? (t % 3) : (t < 18) ? ((t - 9) % 3) : (t < 21) ? (t - 18) : (t - 21);
        float sum = 0.f;
        #pragma unroll
        for (int i = 0; i < 4; i++) {
            const float* r = (const float*)&rv[i][0];
            sum = fmaf(av[i].x, r[0 + o], sum);
            sum = fmaf(av[i].y, r[3 + o], sum);
            sum = fmaf(av[i].z, r[6 + o], sum);
            sum = fmaf(av[i].w, r[9 + o], sum);
        }
        #pragma unroll
        for (int d = 16; d > 0; d >>= 1) sum += __shfl_xor_sync(0xffffffffu, sum, d);
        if (lane == 0) {
            if      (t < 9)  g_M1[j * 9 + t]          = sum;
            else if (t < 18) g_M2[j * 9 + (t - 9)]    = sum;
            else if (t < 21) g_bp1[j * 3 + (t - 18)]  = sum;
            else             g_bp2[j * 3 + (t - 21)]  = sum;
        }
        return;
    }

    // ---- fold GEMM: K=32 chunk per block, split-K partials
    __shared__ float As[64][KCHUNK + 1];
    __shared__ __align__(16) float Bs[KCHUNK][36];

    int ct = bx % 5;              // column tile (5 tiles of 32 -> 160)
    int ks = bx / 5;              // k-split index (0..63)
    int kbase = ks * KCHUNK;

    // batched A loads via float4: 58 rows x 8 float4 = 464, 256 thr -> 2 each
    float4 va[2];
    int    vr[2], vq[2];
    #pragma unroll
    for (int i = 0; i < 2; i++) {
        int idx = tid + 256 * i;
        int r = idx >> 3, q = idx & 7;
        vr[i] = r; vq[i] = q;
        float4 v = make_float4(0.f, 0.f, 0.f, 0.f);
        if (r < NC)       v = *(const float4*)(W_enc + r * D_DIM + kbase + q * 4);
        else if (r == NC) v = *(const float4*)(b_enc + kbase + q * 4);
        va[i] = v;
    }
    // batched B loads (32*32 = 1024 / 256 = 4 each, gathered)
    float vb[4];
    #pragma unroll
    for (int i = 0; i < 4; i++) {
        int idx = tid + 256 * i;
        int kk = idx >> 5, cl = idx & 31;
        int gcol = ct * 32 + cl;
        vb[i] = (gcol < NK) ? fetchB(kbase + kk, gcol, W_shape, W_cam, W_phi, W_leaf, Rf) : 0.f;
    }
    #pragma unroll
    for (int i = 0; i < 2; i++) {
        if (vr[i] < 64) {
            float* dst = &As[vr[i]][vq[i] * 4];
            dst[0] = va[i].x; dst[1] = va[i].y; dst[2] = va[i].z; dst[3] = va[i].w;
        }
    }
    #pragma unroll
    for (int i = 0; i < 4; i++) {
        int idx = tid + 256 * i;
        Bs[idx >> 5][idx & 31] = vb[i];
    }
    __syncthreads();

    // compute: thread = (row r, col group cg of 8)
    int r  = tid >> 2;            // 0..63
    int cg = tid & 3;             // 0..3
    float acc[8];
    #pragma unroll
    for (int e = 0; e < 8; e++) acc[e] = 0.f;
    #pragma unroll
    for (int kk = 0; kk < KCHUNK; kk++) {
        float  xc = As[r][kk];
        float4 w0 = *(const float4*)&Bs[kk][cg * 8];
        float4 w1 = *(const float4*)&Bs[kk][cg * 8 + 4];
        acc[0] = fmaf(xc, w0.x, acc[0]); acc[1] = fmaf(xc, w0.y, acc[1]);
        acc[2] = fmaf(xc, w0.z, acc[2]); acc[3] = fmaf(xc, w0.w, acc[3]);
        acc[4] = fmaf(xc, w1.x, acc[4]); acc[5] = fmaf(xc, w1.y, acc[5]);
        acc[6] = fmaf(xc, w1.z, acc[6]); acc[7] = fmaf(xc, w1.w, acc[7]);
    }
    if (r < 58) {
        float* dst = &g_Wpart[(ks * 58 + r) * NKPAD + ct * 32 + cg * 8];
        *(float4*)dst       = make_float4(acc[0], acc[1], acc[2], acc[3]);
        *(float4*)(dst + 4) = make_float4(acc[4], acc[5], acc[6], acc[7]);
    }
}

// ---------------------------------------------------------------------------
// Kernel B: reduce split-K partials, fold neighbor 3x3 terms AND the root
// (joint 0) subtraction directly into W' and b'. Pads cols [151,160) to 0.
// ---------------------------------------------------------------------------
__global__ void __launch_bounds__(NKPAD)
finalize_kernel(const float* __restrict__ b_shape, const float* __restrict__ b_cam,
                const float* __restrict__ b_phi,   const float* __restrict__ b_leaf,
                const float* __restrict__ init_shape, const float* __restrict__ init_cam,
                const float* __restrict__ reg_b)
{
    int row = blockIdx.x;    // 0..57
    int col = threadIdx.x;   // 0..159
    float s = 0.f;
    #pragma unroll
    for (int p = 0; p < KSPLIT; p++) s += g_Wpart[(p * 58 + row) * NKPAD + col];

    bool isPose = (col >= 79 && col < NK);
    int t = 0, j = 0, o = 0;
    float s0 = 0.f;
    if (isPose) {
        t = col - 79; j = t / 3; o = t - 3 * j;
        #pragma unroll
        for (int p = 0; p < KSPLIT; p++) s0 += g_Wpart[(p * 58 + row) * NKPAD + 79 + o];
    }

    if (row < NC) {
        float w;
        if (col >= NK) {
            w = 0.f;
        } else if (!isPose) {
            w = s;
        } else {
            w = s - s0;
            int a1 = c_NB1[j], a2 = c_NB2[j];
            if (row >= a1 && row < a1 + 3) w += g_M1[j * 9 + (row - a1) * 3 + o];
            if (row >= a2 && row < a2 + 3) w += g_M2[j * 9 + (row - a2) * 3 + o];
            // subtract joint-0 neighbor scatter (NB1[0]=51, NB2[0]=54)
            if (row >= 51 && row < 54) w -= g_M1[(row - 51) * 3 + o];
            if (row >= 54 && row < 57) w -= g_M2[(row - 54) * 3 + o];
        }
        g_W[row * NKPAD + col] = w;
    } else {
        float bv;
        if      (col >= NK) bv = 0.f;
        else if (col < 10)  bv = s + b_shape[col] + init_shape[col];
        else if (col < 13)  bv = s + b_cam[col - 10] + init_cam[col - 10];
        else if (col < 59)  bv = s + b_phi[col - 13];
        else if (col < 79)  bv = s + b_leaf[col - 59];
        else {
            float bt = s  + reg_b[t] + g_bp1[t] + g_bp2[t];
            float b0 = s0 + reg_b[o] + g_bp1[o] + g_bp2[o];
            bv = bt - b0;
        }
        g_b[col] = bv;
    }
}

// ---------------------------------------------------------------------------
// Kernel C: main — out(B,151) = x(B,57) @ W' + b'. Scalar FFMA (proven fast).
// Block = 128 threads covering 64 rows x 16 cols (ty=row, tx=col half of 8).
// grid = (B/64, 10 slices) = 1280 blocks. Batched float4 staging.
// ---------------------------------------------------------------------------
__global__ void __launch_bounds__(TPB)
main_kernel(const float* __restrict__ joints, float* __restrict__ out, int B)
{
    __shared__ __align__(16) float  Xs[RPB * NC];     // 64*57*4 = 14592 B
    __shared__ __align__(16) float4 Ws4[NC][CPB / 4]; // 57*16*4 = 3648 B
    __shared__ float bias_s[CPB];

    const int tid = threadIdx.x;
    const int rb  = blockIdx.x * RPB;
    const int k0  = blockIdx.y * CPB;

    // output section offsets (pose first, per output layout)
    const int CAM_OFF   = B * 72;
    const int PHI_OFF   = CAM_OFF + B * 3;
    const int LEAF_OFF  = PHI_OFF + B * 46;
    const int SHAPE_OFF = LEAF_OFF + B * 20;

    // ---- stage X (batched): 64*57 floats = 912 float4 ----
    if (rb + RPB <= B) {
        const float4* jp = (const float4*)(joints + rb * NC);
        float4 xv[8];
        #pragma unroll
        for (int i = 0; i < 8; i++) {
            int idx = tid + TPB * i;
            if (idx < 912) xv[i] = jp[idx];
        }
        #pragma unroll
        for (int i = 0; i < 8; i++) {
            int idx = tid + TPB * i;
            if (idx < 912) ((float4*)Xs)[idx] = xv[i];
        }
    } else {
        int nr = B - rb;
        for (int idx = tid; idx < nr * NC; idx += TPB)
            Xs[idx] = joints[rb * NC + idx];
    }

    // ---- stage W slice (batched): 57 rows x 4 float4 = 228 float4 ----
    {
        float4 wv[2];
        #pragma unroll
        for (int i = 0; i < 2; i++) {
            int idx = tid + TPB * i;
            if (idx < 228) {
                int r = idx >> 2, q = idx & 3;
                wv[i] = *(const float4*)(g_W + r * NKPAD + k0 + q * 4);
            }
        }
        #pragma unroll
        for (int i = 0; i < 2; i++) {
            int idx = tid + TPB * i;
            if (idx < 228) {
                int r = idx >> 2, q = idx & 3;
                Ws4[r][q] = wv[i];
            }
        }
    }
    if (tid < CPB) bias_s[tid] = g_b[k0 + tid];
    __syncthreads();

    const int ty = tid >> 1;          // row within tile (0..63)
    const int tx = tid & 1;           // column half (0/1)
    const int b  = rb + ty;
    if (b >= B) return;
    const int kb = k0 + tx * 8;       // first of this thread's 8 columns

    float4 a0 = make_float4(bias_s[tx * 8 + 0], bias_s[tx * 8 + 1],
                            bias_s[tx * 8 + 2], bias_s[tx * 8 + 3]);
    float4 a1 = make_float4(bias_s[tx * 8 + 4], bias_s[tx * 8 + 5],
                            bias_s[tx * 8 + 6], bias_s[tx * 8 + 7]);

    const float* xrow = &Xs[ty * NC];
    #pragma unroll
    for (int c = 0; c < NC; c++) {
        float  xc = xrow[c];
        float4 w0 = Ws4[c][tx * 2];
        float4 w1 = Ws4[c][tx * 2 + 1];
        a0.x = fmaf(xc, w0.x, a0.x); a0.y = fmaf(xc, w0.y, a0.y);
        a0.z = fmaf(xc, w0.z, a0.z); a0.w = fmaf(xc, w0.w, a0.w);
        a1.x = fmaf(xc, w1.x, a1.x); a1.y = fmaf(xc, w1.y, a1.y);
        a1.z = fmaf(xc, w1.z, a1.z); a1.w = fmaf(xc, w1.w, a1.w);
    }

    float v[8] = {a0.x, a0.y, a0.z, a0.w, a1.x, a1.y, a1.z, a1.w};
    #pragma unroll
    for (int e = 0; e < 8; e++) {
        int k = kb + e;
        if (k < NK) {
            float val = v[e];
            if      (k < 10) out[SHAPE_OFF + b * 10 + k]        = val;
            else if (k < 13) out[CAM_OFF   + b * 3  + (k - 10)] = val;
            else if (k < 59) out[PHI_OFF   + b * 46 + (k - 13)] = val;
            else if (k < 79) out[LEAF_OFF  + b * 20 + (k - 59)] = val;
            else             out[b * 72 + (k - 79)]             = val;
        }
    }
}

// ---------------------------------------------------------------------------
extern "C" void kernel_launch(void* const* d_in, const int* in_sizes, int n_in,
                              void* d_out, int out_size)
{
    const float* joints     = (const float*)d_in[0];
    const float* W_enc      = (const float*)d_in[1];
    const float* b_enc      = (const float*)d_in[2];
    const float* W_shape    = (const float*)d_in[3];
    const float* b_shape    = (const float*)d_in[4];
    const float* W_cam      = (const float*)d_in[5];
    const float* b_cam      = (const float*)d_in[6];
    const float* W_phi      = (const float*)d_in[7];
    const float* b_phi      = (const float*)d_in[8];
    const float* W_leaf     = (const float*)d_in[9];
    const float* b_leaf     = (const float*)d_in[10];
    const float* init_shape = (const float*)d_in[11];
    const float* init_cam   = (const float*)d_in[12];
    const float* L1_w       = (const float*)d_in[13];
    const float* L1_b       = (const float*)d_in[14];
    const float* L2_w       = (const float*)d_in[15];
    const float* L2_b       = (const float*)d_in[16];
    const float* Rf         = (const float*)d_in[17];
    const float* R1         = (const float*)d_in[18];
    const float* R2         = (const float*)d_in[19];
    const float* reg_b      = (const float*)d_in[20];

    int B = in_sizes[0] / NC;

    precompute_kernel<<<5 * KSPLIT + 72, 256>>>(W_enc, b_enc, W_shape, W_cam, W_phi, W_leaf, Rf,
                                                L1_w, L1_b, L2_w, L2_b, R1, R2);
    finalize_kernel<<<58, NKPAD>>>(b_shape, b_cam, b_phi, b_leaf, init_shape, init_cam, reg_b);
    main_kernel<<<dim3((B + RPB - 1) / RPB, NSLICES), TPB>>>(joints, (float*)d_out, B);
}

// round 7
// speedup vs baseline: 1.1664x; 1.0805x over previous
#include <cuda_runtime.h>

// ---------------------------------------------------------------------------
// Pose2Mesh fully-collapsed linear implementation.
// All heads + neighbor 3x3 contractions + root subtraction folded into one
// dense W'(57 x 151) + b'(151); main kernel = out(B,151) = x(B,57) @ W' + b'.
// ---------------------------------------------------------------------------

#define D_DIM   2048
#define NC      57      // J*3
#define NK      151
#define NKPAD   160
#define KSPLIT  64
#define KCHUNK  32      // D_DIM / KSPLIT
#define H_DIM   512
#define CPB     16      // cols per block (main)
#define NSLICES 10      // 160/16
#define RPB     64      // rows per block (main)
#define TPB     128     // threads per block (main)

// scratch (allocation-free: __device__ globals)
__device__ float g_M1[24 * 9];
__device__ float g_M2[24 * 9];
__device__ float g_bp1[72];
__device__ float g_bp2[72];
__device__ float g_Wpart[KSPLIT * 58 * NKPAD];
__device__ float g_W[NC * NKPAD];
__device__ float g_b[NKPAD];

// NEB1[j]*3 and NEB2[j]*3 (base offsets into the 57-float joint vector)
__constant__ int c_NB1[24] = {51,33,36,51,39,42,51,45,48,54,45,48,54,54,54,54,15,18,21,24,27,30,27,30};
__constant__ int c_NB2[24] = {54,51,51,54,33,36,54,39,42,51,39,42, 0,15,18, 0,54,54,15,18,21,24,21,24};

// ---------------------------------------------------------------------------
// Kernel A (fused): blocks [0, 5*KSPLIT) = fold GEMM split-K partials,
//                   blocks [5*KSPLIT, +72) = per-joint 3x3 M1/M2 + bias dots
// ---------------------------------------------------------------------------
__device__ __forceinline__ float fetchB(int f, int col,
                                        const float* __restrict__ Wsh, const float* __restrict__ Wca,
                                        const float* __restrict__ Wph, const float* __restrict__ Wlf,
                                        const float* __restrict__ Rf)
{
    if (col < 10)  return Wsh[f * 10 + col];
    if (col < 13)  return Wca[f * 3  + (col - 10)];
    if (col < 59)  return Wph[f * 46 + (col - 13)];
    if (col < 79)  return Wlf[f * 20 + (col - 59)];
    int t = col - 79;
    int j = t / 3, o = t - j * 3;
    return Rf[(j * D_DIM + f) * 3 + o];
}

__global__ void __launch_bounds__(256)
precompute_kernel(const float* __restrict__ W_enc, const float* __restrict__ b_enc,
                  const float* __restrict__ W_shape, const float* __restrict__ W_cam,
                  const float* __restrict__ W_phi,   const float* __restrict__ W_leaf,
                  const float* __restrict__ Rf,
                  const float* __restrict__ L1_w, const float* __restrict__ L1_b,
                  const float* __restrict__ L2_w, const float* __restrict__ L2_b,
                  const float* __restrict__ R1,   const float* __restrict__ R2)
{
    int bx  = blockIdx.x;
    int tid = threadIdx.x;

    if (bx >= 5 * KSPLIT) {
        // ---- compute_M: 72 blocks x 8 warps; one warp per (j, t) dot of len 512
        int mb   = bx - 5 * KSPLIT;       // 0..71
        int j    = mb % 24;
        int g    = mb / 24;               // 0..2
        int lane = tid & 31;
        int t    = g * 8 + (tid >> 5);    // 0..23

        const float* ap;
        const float* rp;
        if (t < 9) {
            int c = t / 3, o = t % 3;
            ap = L1_w + (j * 3 + c) * H_DIM;
            rp = R1 + j * H_DIM * 3 + o;
        } else if (t < 18) {
            int tt = t - 9; int c = tt / 3, o = tt % 3;
            ap = L2_w + (j * 3 + c) * H_DIM;
            rp = R2 + j * H_DIM * 3 + o;
        } else if (t < 21) {
            int o = t - 18;
            ap = L1_b + j * H_DIM;
            rp = R1 + j * H_DIM * 3 + o;
        } else {
            int o = t - 21;
            ap = L2_b + j * H_DIM;
            rp = R2 + j * H_DIM * 3 + o;
        }
        // batched scalar loads: full unroll, all 32 LDGs in flight
        float av[16], rv[16];
        #pragma unroll
        for (int i = 0; i < 16; i++) {
            int h = lane + 32 * i;
            av[i] = ap[h];
            rv[i] = rp[h * 3];
        }
        float sum = 0.f;
        #pragma unroll
        for (int i = 0; i < 16; i++) sum = fmaf(av[i], rv[i], sum);
        #pragma unroll
        for (int d = 16; d > 0; d >>= 1) sum += __shfl_xor_sync(0xffffffffu, sum, d);
        if (lane == 0) {
            if      (t < 9)  g_M1[j * 9 + t]          = sum;
            else if (t < 18) g_M2[j * 9 + (t - 9)]    = sum;
            else if (t < 21) g_bp1[j * 3 + (t - 18)]  = sum;
            else             g_bp2[j * 3 + (t - 21)]  = sum;
        }
        return;
    }

    // ---- fold GEMM: K=32 chunk per block, split-K partials
    __shared__ float As[64][KCHUNK + 1];
    __shared__ __align__(16) float Bs[KCHUNK][36];

    int ct = bx % 5;              // column tile (5 tiles of 32 -> 160)
    int ks = bx / 5;              // k-split index (0..63)
    int kbase = ks * KCHUNK;

    // batched A loads via float4: 58 rows x 8 float4 = 464, 256 thr -> 2 each
    float4 va[2];
    int    vr[2], vq[2];
    #pragma unroll
    for (int i = 0; i < 2; i++) {
        int idx = tid + 256 * i;
        int r = idx >> 3, q = idx & 7;
        vr[i] = r; vq[i] = q;
        float4 v = make_float4(0.f, 0.f, 0.f, 0.f);
        if (r < NC)       v = *(const float4*)(W_enc + r * D_DIM + kbase + q * 4);
        else if (r == NC) v = *(const float4*)(b_enc + kbase + q * 4);
        va[i] = v;
    }
    // batched B loads (32*32 = 1024 / 256 = 4 each, gathered)
    float vb[4];
    #pragma unroll
    for (int i = 0; i < 4; i++) {
        int idx = tid + 256 * i;
        int kk = idx >> 5, cl = idx & 31;
        int gcol = ct * 32 + cl;
        vb[i] = (gcol < NK) ? fetchB(kbase + kk, gcol, W_shape, W_cam, W_phi, W_leaf, Rf) : 0.f;
    }
    #pragma unroll
    for (int i = 0; i < 2; i++) {
        if (vr[i] < 64) {
            float* dst = &As[vr[i]][vq[i] * 4];
            dst[0] = va[i].x; dst[1] = va[i].y; dst[2] = va[i].z; dst[3] = va[i].w;
        }
    }
    #pragma unroll
    for (int i = 0; i < 4; i++) {
        int idx = tid + 256 * i;
        Bs[idx >> 5][idx & 31] = vb[i];
    }
    __syncthreads();

    // compute: thread = (row r, col group cg of 8)
    int r  = tid >> 2;            // 0..63
    int cg = tid & 3;             // 0..3
    float acc[8];
    #pragma unroll
    for (int e = 0; e < 8; e++) acc[e] = 0.f;
    #pragma unroll
    for (int kk = 0; kk < KCHUNK; kk++) {
        float  xc = As[r][kk];
        float4 w0 = *(const float4*)&Bs[kk][cg * 8];
        float4 w1 = *(const float4*)&Bs[kk][cg * 8 + 4];
        acc[0] = fmaf(xc, w0.x, acc[0]); acc[1] = fmaf(xc, w0.y, acc[1]);
        acc[2] = fmaf(xc, w0.z, acc[2]); acc[3] = fmaf(xc, w0.w, acc[3]);
        acc[4] = fmaf(xc, w1.x, acc[4]); acc[5] = fmaf(xc, w1.y, acc[5]);
        acc[6] = fmaf(xc, w1.z, acc[6]); acc[7] = fmaf(xc, w1.w, acc[7]);
    }
    if (r < 58) {
        float* dst = &g_Wpart[(ks * 58 + r) * NKPAD + ct * 32 + cg * 8];
        *(float4*)dst       = make_float4(acc[0], acc[1], acc[2], acc[3]);
        *(float4*)(dst + 4) = make_float4(acc[4], acc[5], acc[6], acc[7]);
    }
}

// ---------------------------------------------------------------------------
// Kernel B: reduce split-K partials, fold neighbor 3x3 terms AND the root
// (joint 0) subtraction directly into W' and b'. Pads cols [151,160) to 0.
// ---------------------------------------------------------------------------
__global__ void __launch_bounds__(NKPAD)
finalize_kernel(const float* __restrict__ b_shape, const float* __restrict__ b_cam,
                const float* __restrict__ b_phi,   const float* __restrict__ b_leaf,
                const float* __restrict__ init_shape, const float* __restrict__ init_cam,
                const float* __restrict__ reg_b)
{
    int row = blockIdx.x;    // 0..57
    int col = threadIdx.x;   // 0..159
    float s = 0.f;
    #pragma unroll
    for (int p = 0; p < KSPLIT; p++) s += g_Wpart[(p * 58 + row) * NKPAD + col];

    bool isPose = (col >= 79 && col < NK);
    int t = 0, j = 0, o = 0;
    float s0 = 0.f;
    if (isPose) {
        t = col - 79; j = t / 3; o = t - 3 * j;
        #pragma unroll
        for (int p = 0; p < KSPLIT; p++) s0 += g_Wpart[(p * 58 + row) * NKPAD + 79 + o];
    }

    if (row < NC) {
        float w;
        if (col >= NK) {
            w = 0.f;
        } else if (!isPose) {
            w = s;
        } else {
            w = s - s0;
            int a1 = c_NB1[j], a2 = c_NB2[j];
            if (row >= a1 && row < a1 + 3) w += g_M1[j * 9 + (row - a1) * 3 + o];
            if (row >= a2 && row < a2 + 3) w += g_M2[j * 9 + (row - a2) * 3 + o];
            // subtract joint-0 neighbor scatter (NB1[0]=51, NB2[0]=54)
            if (row >= 51 && row < 54) w -= g_M1[(row - 51) * 3 + o];
            if (row >= 54 && row < 57) w -= g_M2[(row - 54) * 3 + o];
        }
        g_W[row * NKPAD + col] = w;
    } else {
        float bv;
        if      (col >= NK) bv = 0.f;
        else if (col < 10)  bv = s + b_shape[col] + init_shape[col];
        else if (col < 13)  bv = s + b_cam[col - 10] + init_cam[col - 10];
        else if (col < 59)  bv = s + b_phi[col - 13];
        else if (col < 79)  bv = s + b_leaf[col - 59];
        else {
            float bt = s  + reg_b[t] + g_bp1[t] + g_bp2[t];
            float b0 = s0 + reg_b[o] + g_bp1[o] + g_bp2[o];
            bv = bt - b0;
        }
        g_b[col] = bv;
    }
}

// ---------------------------------------------------------------------------
// Kernel C: main — out(B,151) = x(B,57) @ W' + b'. Scalar FFMA.
// Block = 128 threads covering 64 rows x 16 cols (ty=row, tx=col half of 8).
// Results staged in smem then stored with 16-float contiguous runs per row
// (coalesced: ~4 sectors/warp-store instead of ~32 for strided direct stores).
// grid = (B/64, 10 slices) = 1280 blocks.
// ---------------------------------------------------------------------------
__global__ void __launch_bounds__(TPB)
main_kernel(const float* __restrict__ joints, float* __restrict__ out, int B)
{
    __shared__ __align__(16) float  Xs[RPB * NC];     // 64*57*4 = 14592 B
    __shared__ __align__(16) float4 Ws4[NC][CPB / 4]; // 57*16*4 = 3648 B
    __shared__ float bias_s[CPB];
    __shared__ __align__(16) float  Os[RPB * CPB];    // 64*16*4 = 4096 B

    const int tid = threadIdx.x;
    const int rb  = blockIdx.x * RPB;
    const int k0  = blockIdx.y * CPB;

    // output section offsets (pose first, per output layout)
    const int CAM_OFF   = B * 72;
    const int PHI_OFF   = CAM_OFF + B * 3;
    const int LEAF_OFF  = PHI_OFF + B * 46;
    const int SHAPE_OFF = LEAF_OFF + B * 20;

    // ---- stage X (batched): 64*57 floats = 912 float4 ----
    if (rb + RPB <= B) {
        const float4* jp = (const float4*)(joints + rb * NC);
        float4 xv[8];
        #pragma unroll
        for (int i = 0; i < 8; i++) {
            int idx = tid + TPB * i;
            if (idx < 912) xv[i] = jp[idx];
        }
        #pragma unroll
        for (int i = 0; i < 8; i++) {
            int idx = tid + TPB * i;
            if (idx < 912) ((float4*)Xs)[idx] = xv[i];
        }
    } else {
        int nr = B - rb;
        for (int idx = tid; idx < nr * NC; idx += TPB)
            Xs[idx] = joints[rb * NC + idx];
    }

    // ---- stage W slice (batched): 57 rows x 4 float4 = 228 float4 ----
    {
        float4 wv[2];
        #pragma unroll
        for (int i = 0; i < 2; i++) {
            int idx = tid + TPB * i;
            if (idx < 228) {
                int r = idx >> 2, q = idx & 3;
                wv[i] = *(const float4*)(g_W + r * NKPAD + k0 + q * 4);
            }
        }
        #pragma unroll
        for (int i = 0; i < 2; i++) {
            int idx = tid + TPB * i;
            if (idx < 228) {
                int r = idx >> 2, q = idx & 3;
                Ws4[r][q] = wv[i];
            }
        }
    }
    if (tid < CPB) bias_s[tid] = g_b[k0 + tid];
    __syncthreads();

    const int ty = tid >> 1;          // row within tile (0..63)
    const int tx = tid & 1;           // column half (0/1)

    {
        float4 a0 = make_float4(bias_s[tx * 8 + 0], bias_s[tx * 8 + 1],
                                bias_s[tx * 8 + 2], bias_s[tx * 8 + 3]);
        float4 a1 = make_float4(bias_s[tx * 8 + 4], bias_s[tx * 8 + 5],
                                bias_s[tx * 8 + 6], bias_s[tx * 8 + 7]);

        const float* xrow = &Xs[ty * NC];
        #pragma unroll
        for (int c = 0; c < NC; c++) {
            float  xc = xrow[c];
            float4 w0 = Ws4[c][tx * 2];
            float4 w1 = Ws4[c][tx * 2 + 1];
            a0.x = fmaf(xc, w0.x, a0.x); a0.y = fmaf(xc, w0.y, a0.y);
            a0.z = fmaf(xc, w0.z, a0.z); a0.w = fmaf(xc, w0.w, a0.w);
            a1.x = fmaf(xc, w1.x, a1.x); a1.y = fmaf(xc, w1.y, a1.y);
            a1.z = fmaf(xc, w1.z, a1.z); a1.w = fmaf(xc, w1.w, a1.w);
        }

        float4* op = (float4*)&Os[ty * CPB + tx * 8];
        op[0] = a0;
        op[1] = a1;
    }
    __syncthreads();

    // ---- coalesced store: warp covers 2 rows x 16 consecutive k ----
    #pragma unroll
    for (int i = 0; i < 8; i++) {
        int idx = tid + TPB * i;          // 0..1023
        int e = idx & (CPB - 1);
        int r = idx >> 4;
        int k = k0 + e;
        int b = rb + r;
        if (k < NK && b < B) {
            float val = Os[idx];
            if      (k < 10) out[SHAPE_OFF + b * 10 + k]        = val;
            else if (k < 13) out[CAM_OFF   + b * 3  + (k - 10)] = val;
            else if (k < 59) out[PHI_OFF   + b * 46 + (k - 13)] = val;
            else if (k < 79) out[LEAF_OFF  + b * 20 + (k - 59)] = val;
            else             out[b * 72 + (k - 79)]             = val;
        }
    }
}

// ---------------------------------------------------------------------------
extern "C" void kernel_launch(void* const* d_in, const int* in_sizes, int n_in,
                              void* d_out, int out_size)
{
    const float* joints     = (const float*)d_in[0];
    const float* W_enc      = (const float*)d_in[1];
    const float* b_enc      = (const float*)d_in[2];
    const float* W_shape    = (const float*)d_in[3];
    const float* b_shape    = (const float*)d_in[4];
    const float* W_cam      = (const float*)d_in[5];
    const float* b_cam      = (const float*)d_in[6];
    const float* W_phi      = (const float*)d_in[7];
    const float* b_phi      = (const float*)d_in[8];
    const float* W_leaf     = (const float*)d_in[9];
    const float* b_leaf     = (const float*)d_in[10];
    const float* init_shape = (const float*)d_in[11];
    const float* init_cam   = (const float*)d_in[12];
    const float* L1_w       = (const float*)d_in[13];
    const float* L1_b       = (const float*)d_in[14];
    const float* L2_w       = (const float*)d_in[15];
    const float* L2_b       = (const float*)d_in[16];
    const float* Rf         = (const float*)d_in[17];
    const float* R1         = (const float*)d_in[18];
    const float* R2         = (const float*)d_in[19];
    const float* reg_b      = (const float*)d_in[20];

    int B = in_sizes[0] / NC;

    precompute_kernel<<<5 * KSPLIT + 72, 256>>>(W_enc, b_enc, W_shape, W_cam, W_phi, W_leaf, Rf,
                                                L1_w, L1_b, L2_w, L2_b, R1, R2);
    finalize_kernel<<<58, NKPAD>>>(b_shape, b_cam, b_phi, b_leaf, init_shape, init_cam, reg_b);
    main_kernel<<<dim3((B + RPB - 1) / RPB, NSLICES), TPB>>>(joints, (float*)d_out, B);
}

// round 8
// speedup vs baseline: 1.1892x; 1.0195x over previous
#include <cuda_runtime.h>

// ---------------------------------------------------------------------------
// Pose2Mesh fully-collapsed linear implementation.
// All heads + neighbor 3x3 contractions + root subtraction folded into one
// dense W'(57 x 151) + b'(151); main kernel = out(B,151) = x(B,57) @ W' + b'.
// Launches chained with programmatic stream serialization to overlap launch
// overhead (no semantic change: no device-side trigger is used).
// ---------------------------------------------------------------------------

#define D_DIM   2048
#define NC      57      // J*3
#define NK      151
#define NKPAD   160
#define KSPLIT  64
#define KCHUNK  32      // D_DIM / KSPLIT
#define H_DIM   512
#define CPB     16      // cols per block (main)
#define NSLICES 10      // 160/16
#define RPB     64      // rows per block (main)
#define TPB     128     // threads per block (main)

// scratch (allocation-free: __device__ globals)
__device__ float g_M1[24 * 9];
__device__ float g_M2[24 * 9];
__device__ float g_bp1[72];
__device__ float g_bp2[72];
__device__ float g_Wpart[KSPLIT * 58 * NKPAD];
__device__ float g_W[NC * NKPAD];
__device__ float g_b[NKPAD];

// NEB1[j]*3 and NEB2[j]*3 (base offsets into the 57-float joint vector)
__constant__ int c_NB1[24] = {51,33,36,51,39,42,51,45,48,54,45,48,54,54,54,54,15,18,21,24,27,30,27,30};
__constant__ int c_NB2[24] = {54,51,51,54,33,36,54,39,42,51,39,42, 0,15,18, 0,54,54,15,18,21,24,21,24};

// ---------------------------------------------------------------------------
// Kernel A (fused): blocks [0, 5*KSPLIT) = fold GEMM split-K partials,
//                   blocks [5*KSPLIT, +48) = per-(joint, side) M/bias dots
// ---------------------------------------------------------------------------
__device__ __forceinline__ float fetchB(int f, int col,
                                        const float* __restrict__ Wsh, const float* __restrict__ Wca,
                                        const float* __restrict__ Wph, const float* __restrict__ Wlf,
                                        const float* __restrict__ Rf)
{
    if (col < 10)  return Wsh[f * 10 + col];
    if (col < 13)  return Wca[f * 3  + (col - 10)];
    if (col < 59)  return Wph[f * 46 + (col - 13)];
    if (col < 79)  return Wlf[f * 20 + (col - 59)];
    int t = col - 79;
    int j = t / 3, o = t - j * 3;
    return Rf[(j * D_DIM + f) * 3 + o];
}

__global__ void __launch_bounds__(256)
precompute_kernel(const float* __restrict__ W_enc, const float* __restrict__ b_enc,
                  const float* __restrict__ W_shape, const float* __restrict__ W_cam,
                  const float* __restrict__ W_phi,   const float* __restrict__ W_leaf,
                  const float* __restrict__ Rf,
                  const float* __restrict__ L1_w, const float* __restrict__ L1_b,
                  const float* __restrict__ L2_w, const float* __restrict__ L2_b,
                  const float* __restrict__ R1,   const float* __restrict__ R2)
{
    int bx  = blockIdx.x;
    int tid = threadIdx.x;

    if (bx >= 5 * KSPLIT) {
        // ---- M-part: 48 blocks = (j, s). Load L_s_w[j], L_s_b[j], R_s[j] ONCE
        // (coalesced float4 -> smem), then 12 dots (9 M + 3 bias) from smem.
        __shared__ __align__(16) float sLw[3 * H_DIM];   // 1536
        __shared__ __align__(16) float sR [H_DIM * 3];   // 1536
        __shared__ __align__(16) float sLb[H_DIM];       // 512

        int mb = bx - 5 * KSPLIT;         // 0..47
        int j  = mb >> 1;
        int s  = mb & 1;
        const float* Lw = (s ? L2_w : L1_w) + j * 3 * H_DIM;
        const float* Lb = (s ? L2_b : L1_b) + j * H_DIM;
        const float* Rm = (s ? R2   : R1  ) + j * H_DIM * 3;

        // 896 float4 total: 384 Lw + 384 R + 128 Lb; 4 per thread (guarded)
        float4 v[4];
        #pragma unroll
        for (int i = 0; i < 4; i++) {
            int idx = tid + 256 * i;
            if      (idx < 384) v[i] = *(const float4*)(Lw + idx * 4);
            else if (idx < 768) v[i] = *(const float4*)(Rm + (idx - 384) * 4);
            else if (idx < 896) v[i] = *(const float4*)(Lb + (idx - 768) * 4);
        }
        #pragma unroll
        for (int i = 0; i < 4; i++) {
            int idx = tid + 256 * i;
            if      (idx < 384) *(float4*)(sLw + idx * 4)         = v[i];
            else if (idx < 768) *(float4*)(sR  + (idx - 384) * 4) = v[i];
            else if (idx < 896) *(float4*)(sLb + (idx - 768) * 4) = v[i];
        }
        __syncthreads();

        int lane = tid & 31;
        int w    = tid >> 5;              // 0..7
        for (int t = w; t < 12; t += 8) {
            // tasks 0..8: M[c][o] = sum_h Lw[c*512+h]*R[h*3+o]
            // tasks 9..11: bp[o]  = sum_h Lb[h]*R[h*3+o]
            int c = (t < 9) ? (t / 3) : 0;
            int o = (t < 9) ? (t % 3) : (t - 9);
            const float* ap = (t < 9) ? (sLw + c * H_DIM) : sLb;
            float sum = 0.f;
            #pragma unroll
            for (int i = 0; i < 16; i++) {
                int h = lane + 32 * i;
                sum = fmaf(ap[h], sR[h * 3 + o], sum);
            }
            #pragma unroll
            for (int d = 16; d > 0; d >>= 1) sum += __shfl_xor_sync(0xffffffffu, sum, d);
            if (lane == 0) {
                if (t < 9) { if (s) g_M2[j * 9 + t] = sum; else g_M1[j * 9 + t] = sum; }
                else       { if (s) g_bp2[j * 3 + o] = sum; else g_bp1[j * 3 + o] = sum; }
            }
        }
        return;
    }

    // ---- fold GEMM: K=32 chunk per block, split-K partials
    __shared__ float As[64][KCHUNK + 1];
    __shared__ __align__(16) float Bs[KCHUNK][36];

    int ct = bx % 5;              // column tile (5 tiles of 32 -> 160)
    int ks = bx / 5;              // k-split index (0..63)
    int kbase = ks * KCHUNK;

    // batched A loads via float4: 58 rows x 8 float4 = 464, 256 thr -> 2 each
    float4 va[2];
    int    vr[2], vq[2];
    #pragma unroll
    for (int i = 0; i < 2; i++) {
        int idx = tid + 256 * i;
        int r = idx >> 3, q = idx & 7;
        vr[i] = r; vq[i] = q;
        float4 v4 = make_float4(0.f, 0.f, 0.f, 0.f);
        if (r < NC)       v4 = *(const float4*)(W_enc + r * D_DIM + kbase + q * 4);
        else if (r == NC) v4 = *(const float4*)(b_enc + kbase + q * 4);
        va[i] = v4;
    }
    // batched B loads (32*32 = 1024 / 256 = 4 each, gathered)
    float vb[4];
    #pragma unroll
    for (int i = 0; i < 4; i++) {
        int idx = tid + 256 * i;
        int kk = idx >> 5, cl = idx & 31;
        int gcol = ct * 32 + cl;
        vb[i] = (gcol < NK) ? fetchB(kbase + kk, gcol, W_shape, W_cam, W_phi, W_leaf, Rf) : 0.f;
    }
    #pragma unroll
    for (int i = 0; i < 2; i++) {
        if (vr[i] < 64) {
            float* dst = &As[vr[i]][vq[i] * 4];
            dst[0] = va[i].x; dst[1] = va[i].y; dst[2] = va[i].z; dst[3] = va[i].w;
        }
    }
    #pragma unroll
    for (int i = 0; i < 4; i++) {
        int idx = tid + 256 * i;
        Bs[idx >> 5][idx & 31] = vb[i];
    }
    __syncthreads();

    // compute: thread = (row r, col group cg of 8)
    int r  = tid >> 2;            // 0..63
    int cg = tid & 3;             // 0..3
    float acc[8];
    #pragma unroll
    for (int e = 0; e < 8; e++) acc[e] = 0.f;
    #pragma unroll
    for (int kk = 0; kk < KCHUNK; kk++) {
        float  xc = As[r][kk];
        float4 w0 = *(const float4*)&Bs[kk][cg * 8];
        float4 w1 = *(const float4*)&Bs[kk][cg * 8 + 4];
        acc[0] = fmaf(xc, w0.x, acc[0]); acc[1] = fmaf(xc, w0.y, acc[1]);
        acc[2] = fmaf(xc, w0.z, acc[2]); acc[3] = fmaf(xc, w0.w, acc[3]);
        acc[4] = fmaf(xc, w1.x, acc[4]); acc[5] = fmaf(xc, w1.y, acc[5]);
        acc[6] = fmaf(xc, w1.z, acc[6]); acc[7] = fmaf(xc, w1.w, acc[7]);
    }
    if (r < 58) {
        float* dst = &g_Wpart[(ks * 58 + r) * NKPAD + ct * 32 + cg * 8];
        *(float4*)dst       = make_float4(acc[0], acc[1], acc[2], acc[3]);
        *(float4*)(dst + 4) = make_float4(acc[4], acc[5], acc[6], acc[7]);
    }
}

// ---------------------------------------------------------------------------
// Kernel B: reduce split-K partials, fold neighbor 3x3 terms AND the root
// (joint 0) subtraction directly into W' and b'. Pads cols [151,160) to 0.
// ---------------------------------------------------------------------------
__global__ void __launch_bounds__(NKPAD)
finalize_kernel(const float* __restrict__ b_shape, const float* __restrict__ b_cam,
                const float* __restrict__ b_phi,   const float* __restrict__ b_leaf,
                const float* __restrict__ init_shape, const float* __restrict__ init_cam,
                const float* __restrict__ reg_b)
{
    int row = blockIdx.x;    // 0..57
    int col = threadIdx.x;   // 0..159
    float s = 0.f;
    #pragma unroll
    for (int p = 0; p < KSPLIT; p++) s += g_Wpart[(p * 58 + row) * NKPAD + col];

    bool isPose = (col >= 79 && col < NK);
    int t = 0, j = 0, o = 0;
    float s0 = 0.f;
    if (isPose) {
        t = col - 79; j = t / 3; o = t - 3 * j;
        #pragma unroll
        for (int p = 0; p < KSPLIT; p++) s0 += g_Wpart[(p * 58 + row) * NKPAD + 79 + o];
    }

    if (row < NC) {
        float w;
        if (col >= NK) {
            w = 0.f;
        } else if (!isPose) {
            w = s;
        } else {
            w = s - s0;
            int a1 = c_NB1[j], a2 = c_NB2[j];
            if (row >= a1 && row < a1 + 3) w += g_M1[j * 9 + (row - a1) * 3 + o];
            if (row >= a2 && row < a2 + 3) w += g_M2[j * 9 + (row - a2) * 3 + o];
            // subtract joint-0 neighbor scatter (NB1[0]=51, NB2[0]=54)
            if (row >= 51 && row < 54) w -= g_M1[(row - 51) * 3 + o];
            if (row >= 54 && row < 57) w -= g_M2[(row - 54) * 3 + o];
        }
        g_W[row * NKPAD + col] = w;
    } else {
        float bv;
        if      (col >= NK) bv = 0.f;
        else if (col < 10)  bv = s + b_shape[col] + init_shape[col];
        else if (col < 13)  bv = s + b_cam[col - 10] + init_cam[col - 10];
        else if (col < 59)  bv = s + b_phi[col - 13];
        else if (col < 79)  bv = s + b_leaf[col - 59];
        else {
            float bt = s  + reg_b[t] + g_bp1[t] + g_bp2[t];
            float b0 = s0 + reg_b[o] + g_bp1[o] + g_bp2[o];
            bv = bt - b0;
        }
        g_b[col] = bv;
    }
}

// ---------------------------------------------------------------------------
// Kernel C: main — out(B,151) = x(B,57) @ W' + b'. Scalar FFMA.
// Block = 128 threads covering 64 rows x 16 cols; results staged in smem,
// stored as 16-float contiguous runs (coalesced). grid = (B/64, 10 slices).
// ---------------------------------------------------------------------------
__global__ void __launch_bounds__(TPB)
main_kernel(const float* __restrict__ joints, float* __restrict__ out, int B)
{
    __shared__ __align__(16) float  Xs[RPB * NC];     // 64*57*4 = 14592 B
    __shared__ __align__(16) float4 Ws4[NC][CPB / 4]; // 57*16*4 = 3648 B
    __shared__ float bias_s[CPB];
    __shared__ __align__(16) float  Os[RPB * CPB];    // 64*16*4 = 4096 B

    const int tid = threadIdx.x;
    const int rb  = blockIdx.x * RPB;
    const int k0  = blockIdx.y * CPB;

    // output section offsets (pose first, per output layout)
    const int CAM_OFF   = B * 72;
    const int PHI_OFF   = CAM_OFF + B * 3;
    const int LEAF_OFF  = PHI_OFF + B * 46;
    const int SHAPE_OFF = LEAF_OFF + B * 20;

    // ---- stage X (batched): 64*57 floats = 912 float4 ----
    if (rb + RPB <= B) {
        const float4* jp = (const float4*)(joints + rb * NC);
        float4 xv[8];
        #pragma unroll
        for (int i = 0; i < 8; i++) {
            int idx = tid + TPB * i;
            if (idx < 912) xv[i] = jp[idx];
        }
        #pragma unroll
        for (int i = 0; i < 8; i++) {
            int idx = tid + TPB * i;
            if (idx < 912) ((float4*)Xs)[idx] = xv[i];
        }
    } else {
        int nr = B - rb;
        for (int idx = tid; idx < nr * NC; idx += TPB)
            Xs[idx] = joints[rb * NC + idx];
    }

    // ---- stage W slice (batched): 57 rows x 4 float4 = 228 float4 ----
    {
        float4 wv[2];
        #pragma unroll
        for (int i = 0; i < 2; i++) {
            int idx = tid + TPB * i;
            if (idx < 228) {
                int r = idx >> 2, q = idx & 3;
                wv[i] = *(const float4*)(g_W + r * NKPAD + k0 + q * 4);
            }
        }
        #pragma unroll
        for (int i = 0; i < 2; i++) {
            int idx = tid + TPB * i;
            if (idx < 228) {
                int r = idx >> 2, q = idx & 3;
                Ws4[r][q] = wv[i];
            }
        }
    }
    if (tid < CPB) bias_s[tid] = g_b[k0 + tid];
    __syncthreads();

    const int ty = tid >> 1;          // row within tile (0..63)
    const int tx = tid & 1;           // column half (0/1)

    {
        float4 a0 = make_float4(bias_s[tx * 8 + 0], bias_s[tx * 8 + 1],
                                bias_s[tx * 8 + 2], bias_s[tx * 8 + 3]);
        float4 a1 = make_float4(bias_s[tx * 8 + 4], bias_s[tx * 8 + 5],
                                bias_s[tx * 8 + 6], bias_s[tx * 8 + 7]);

        const float* xrow = &Xs[ty * NC];
        #pragma unroll
        for (int c = 0; c < NC; c++) {
            float  xc = xrow[c];
            float4 w0 = Ws4[c][tx * 2];
            float4 w1 = Ws4[c][tx * 2 + 1];
            a0.x = fmaf(xc, w0.x, a0.x); a0.y = fmaf(xc, w0.y, a0.y);
            a0.z = fmaf(xc, w0.z, a0.z); a0.w = fmaf(xc, w0.w, a0.w);
            a1.x = fmaf(xc, w1.x, a1.x); a1.y = fmaf(xc, w1.y, a1.y);
            a1.z = fmaf(xc, w1.z, a1.z); a1.w = fmaf(xc, w1.w, a1.w);
        }

        float4* op = (float4*)&Os[ty * CPB + tx * 8];
        op[0] = a0;
        op[1] = a1;
    }
    __syncthreads();

    // ---- coalesced store: warp covers 2 rows x 16 consecutive k ----
    #pragma unroll
    for (int i = 0; i < 8; i++) {
        int idx = tid + TPB * i;          // 0..1023
        int e = idx & (CPB - 1);
        int r = idx >> 4;
        int k = k0 + e;
        int b = rb + r;
        if (k < NK && b < B) {
            float val = Os[idx];
            if      (k < 10) out[SHAPE_OFF + b * 10 + k]        = val;
            else if (k < 13) out[CAM_OFF   + b * 3  + (k - 10)] = val;
            else if (k < 59) out[PHI_OFF   + b * 46 + (k - 13)] = val;
            else if (k < 79) out[LEAF_OFF  + b * 20 + (k - 59)] = val;
            else             out[b * 72 + (k - 79)]             = val;
        }
    }
}

// ---------------------------------------------------------------------------
extern "C" void kernel_launch(void* const* d_in, const int* in_sizes, int n_in,
                              void* d_out, int out_size)
{
    const float* joints     = (const float*)d_in[0];
    const float* W_enc      = (const float*)d_in[1];
    const float* b_enc      = (const float*)d_in[2];
    const float* W_shape    = (const float*)d_in[3];
    const float* b_shape    = (const float*)d_in[4];
    const float* W_cam      = (const float*)d_in[5];
    const float* b_cam      = (const float*)d_in[6];
    const float* W_phi      = (const float*)d_in[7];
    const float* b_phi      = (const float*)d_in[8];
    const float* W_leaf     = (const float*)d_in[9];
    const float* b_leaf     = (const float*)d_in[10];
    const float* init_shape = (const float*)d_in[11];
    const float* init_cam   = (const float*)d_in[12];
    const float* L1_w       = (const float*)d_in[13];
    const float* L1_b       = (const float*)d_in[14];
    const float* L2_w       = (const float*)d_in[15];
    const float* L2_b       = (const float*)d_in[16];
    const float* Rf         = (const float*)d_in[17];
    const float* R1         = (const float*)d_in[18];
    const float* R2         = (const float*)d_in[19];
    const float* reg_b      = (const float*)d_in[20];

    int B = in_sizes[0] / NC;
    float* outf = (float*)d_out;

    // Kernel 1: normal launch
    precompute_kernel<<<5 * KSPLIT + 48, 256>>>(W_enc, b_enc, W_shape, W_cam, W_phi, W_leaf, Rf,
                                                L1_w, L1_b, L2_w, L2_b, R1, R2);

    // Kernels 2+3: programmatic stream serialization — downstream grid setup
    // overlaps upstream execution; execution still starts only at upstream
    // completion (no device-side trigger is used), so semantics are unchanged.
    cudaLaunchAttribute pssAttr[1];
    pssAttr[0].id = cudaLaunchAttributeProgrammaticStreamSerialization;
    pssAttr[0].val.programmaticStreamSerializationAllowed = 1;

    {
        cudaLaunchConfig_t cfg = {};
        cfg.gridDim  = dim3(58);
        cfg.blockDim = dim3(NKPAD);
        cfg.attrs    = pssAttr;
        cfg.numAttrs = 1;
        cudaLaunchKernelEx(&cfg, finalize_kernel,
                           b_shape, b_cam, b_phi, b_leaf, init_shape, init_cam, reg_b);
    }
    {
        cudaLaunchConfig_t cfg = {};
        cfg.gridDim  = dim3((B + RPB - 1) / RPB, NSLICES);
        cfg.blockDim = dim3(TPB);
        cfg.attrs    = pssAttr;
        cfg.numAttrs = 1;
        cudaLaunchKernelEx(&cfg, main_kernel, joints, outf, B);
    }
}

// round 9
// speedup vs baseline: 1.2110x; 1.0184x over previous
#include <cuda_runtime.h>

// ---------------------------------------------------------------------------
// Pose2Mesh fully-collapsed linear implementation.
// All heads + neighbor 3x3 contractions + root subtraction folded into one
// dense W'(57 x 151) + b'(151); main kernel = out(B,151) = x(B,57) @ W' + b'.
// Kernels chained with TRUE programmatic dependent launch: upstream triggers
// at entry (safe: griddepcontrol.wait blocks until the full upstream grid
// completes), downstream overlaps its launch + independent pre-work.
// ---------------------------------------------------------------------------

#define D_DIM   2048
#define NC      57      // J*3
#define NK      151
#define NKPAD   160
#define KSPLIT  64
#define KCHUNK  32      // D_DIM / KSPLIT
#define H_DIM   512
#define CPB     16      // cols per block (main)
#define NSLICES 10      // 160/16
#define RPB     64      // rows per block (main)
#define TPB     128     // threads per block (main)

#define GDC_LAUNCH() asm volatile("griddepcontrol.launch_dependents;")
#define GDC_WAIT()   asm volatile("griddepcontrol.wait;" ::: "memory")

// scratch (allocation-free: __device__ globals)
__device__ float g_M1[24 * 9];
__device__ float g_M2[24 * 9];
__device__ float g_bp1[72];
__device__ float g_bp2[72];
__device__ float g_Wpart[KSPLIT * 58 * NKPAD];
__device__ float g_W[NC * NKPAD];
__device__ float g_b[NKPAD];

// NEB1[j]*3 and NEB2[j]*3 (base offsets into the 57-float joint vector)
__constant__ int c_NB1[24] = {51,33,36,51,39,42,51,45,48,54,45,48,54,54,54,54,15,18,21,24,27,30,27,30};
__constant__ int c_NB2[24] = {54,51,51,54,33,36,54,39,42,51,39,42, 0,15,18, 0,54,54,15,18,21,24,21,24};

// ---------------------------------------------------------------------------
// Kernel A (fused): blocks [0, 5*KSPLIT) = fold GEMM split-K partials,
//                   blocks [5*KSPLIT, +48) = per-(joint, side) M/bias dots
// ---------------------------------------------------------------------------
__device__ __forceinline__ float fetchB(int f, int col,
                                        const float* __restrict__ Wsh, const float* __restrict__ Wca,
                                        const float* __restrict__ Wph, const float* __restrict__ Wlf,
                                        const float* __restrict__ Rf)
{
    if (col < 10)  return Wsh[f * 10 + col];
    if (col < 13)  return Wca[f * 3  + (col - 10)];
    if (col < 59)  return Wph[f * 46 + (col - 13)];
    if (col < 79)  return Wlf[f * 20 + (col - 59)];
    int t = col - 79;
    int j = t / 3, o = t - j * 3;
    return Rf[(j * D_DIM + f) * 3 + o];
}

__global__ void __launch_bounds__(256)
precompute_kernel(const float* __restrict__ W_enc, const float* __restrict__ b_enc,
                  const float* __restrict__ W_shape, const float* __restrict__ W_cam,
                  const float* __restrict__ W_phi,   const float* __restrict__ W_leaf,
                  const float* __restrict__ Rf,
                  const float* __restrict__ L1_w, const float* __restrict__ L1_b,
                  const float* __restrict__ L2_w, const float* __restrict__ L2_b,
                  const float* __restrict__ R1,   const float* __restrict__ R2)
{
    GDC_LAUNCH();   // let finalize launch + prologue overlap our execution

    int bx  = blockIdx.x;
    int tid = threadIdx.x;

    if (bx >= 5 * KSPLIT) {
        // ---- M-part: 48 blocks = (j, s). Load L_s_w[j], L_s_b[j], R_s[j] ONCE
        // (coalesced float4 -> smem), then 12 dots (9 M + 3 bias) from smem.
        __shared__ __align__(16) float sLw[3 * H_DIM];   // 1536
        __shared__ __align__(16) float sR [H_DIM * 3];   // 1536
        __shared__ __align__(16) float sLb[H_DIM];       // 512

        int mb = bx - 5 * KSPLIT;         // 0..47
        int j  = mb >> 1;
        int s  = mb & 1;
        const float* Lw = (s ? L2_w : L1_w) + j * 3 * H_DIM;
        const float* Lb = (s ? L2_b : L1_b) + j * H_DIM;
        const float* Rm = (s ? R2   : R1  ) + j * H_DIM * 3;

        // 896 float4 total: 384 Lw + 384 R + 128 Lb; 4 per thread (guarded)
        float4 v[4];
        #pragma unroll
        for (int i = 0; i < 4; i++) {
            int idx = tid + 256 * i;
            if      (idx < 384) v[i] = *(const float4*)(Lw + idx * 4);
            else if (idx < 768) v[i] = *(const float4*)(Rm + (idx - 384) * 4);
            else if (idx < 896) v[i] = *(const float4*)(Lb + (idx - 768) * 4);
        }
        #pragma unroll
        for (int i = 0; i < 4; i++) {
            int idx = tid + 256 * i;
            if      (idx < 384) *(float4*)(sLw + idx * 4)         = v[i];
            else if (idx < 768) *(float4*)(sR  + (idx - 384) * 4) = v[i];
            else if (idx < 896) *(float4*)(sLb + (idx - 768) * 4) = v[i];
        }
        __syncthreads();

        int lane = tid & 31;
        int w    = tid >> 5;              // 0..7
        for (int t = w; t < 12; t += 8) {
            // tasks 0..8: M[c][o] = sum_h Lw[c*512+h]*R[h*3+o]
            // tasks 9..11: bp[o]  = sum_h Lb[h]*R[h*3+o]
            int c = (t < 9) ? (t / 3) : 0;
            int o = (t < 9) ? (t % 3) : (t - 9);
            const float* ap = (t < 9) ? (sLw + c * H_DIM) : sLb;
            float sum = 0.f;
            #pragma unroll
            for (int i = 0; i < 16; i++) {
                int h = lane + 32 * i;
                sum = fmaf(ap[h], sR[h * 3 + o], sum);
            }
            #pragma unroll
            for (int d = 16; d > 0; d >>= 1) sum += __shfl_xor_sync(0xffffffffu, sum, d);
            if (lane == 0) {
                if (t < 9) { if (s) g_M2[j * 9 + t] = sum; else g_M1[j * 9 + t] = sum; }
                else       { if (s) g_bp2[j * 3 + o] = sum; else g_bp1[j * 3 + o] = sum; }
            }
        }
        return;
    }

    // ---- fold GEMM: K=32 chunk per block, split-K partials
    __shared__ float As[64][KCHUNK + 1];
    __shared__ __align__(16) float Bs[KCHUNK][36];

    int ct = bx % 5;              // column tile (5 tiles of 32 -> 160)
    int ks = bx / 5;              // k-split index (0..63)
    int kbase = ks * KCHUNK;

    // batched A loads via float4: 58 rows x 8 float4 = 464, 256 thr -> 2 each
    float4 va[2];
    int    vr[2], vq[2];
    #pragma unroll
    for (int i = 0; i < 2; i++) {
        int idx = tid + 256 * i;
        int r = idx >> 3, q = idx & 7;
        vr[i] = r; vq[i] = q;
        float4 v4 = make_float4(0.f, 0.f, 0.f, 0.f);
        if (r < NC)       v4 = *(const float4*)(W_enc + r * D_DIM + kbase + q * 4);
        else if (r == NC) v4 = *(const float4*)(b_enc + kbase + q * 4);
        va[i] = v4;
    }
    // batched B loads (32*32 = 1024 / 256 = 4 each, gathered)
    float vb[4];
    #pragma unroll
    for (int i = 0; i < 4; i++) {
        int idx = tid + 256 * i;
        int kk = idx >> 5, cl = idx & 31;
        int gcol = ct * 32 + cl;
        vb[i] = (gcol < NK) ? fetchB(kbase + kk, gcol, W_shape, W_cam, W_phi, W_leaf, Rf) : 0.f;
    }
    #pragma unroll
    for (int i = 0; i < 2; i++) {
        if (vr[i] < 64) {
            float* dst = &As[vr[i]][vq[i] * 4];
            dst[0] = va[i].x; dst[1] = va[i].y; dst[2] = va[i].z; dst[3] = va[i].w;
        }
    }
    #pragma unroll
    for (int i = 0; i < 4; i++) {
        int idx = tid + 256 * i;
        Bs[idx >> 5][idx & 31] = vb[i];
    }
    __syncthreads();

    // compute: thread = (row r, col group cg of 8)
    int r  = tid >> 2;            // 0..63
    int cg = tid & 3;             // 0..3
    float acc[8];
    #pragma unroll
    for (int e = 0; e < 8; e++) acc[e] = 0.f;
    #pragma unroll
    for (int kk = 0; kk < KCHUNK; kk++) {
        float  xc = As[r][kk];
        float4 w0 = *(const float4*)&Bs[kk][cg * 8];
        float4 w1 = *(const float4*)&Bs[kk][cg * 8 + 4];
        acc[0] = fmaf(xc, w0.x, acc[0]); acc[1] = fmaf(xc, w0.y, acc[1]);
        acc[2] = fmaf(xc, w0.z, acc[2]); acc[3] = fmaf(xc, w0.w, acc[3]);
        acc[4] = fmaf(xc, w1.x, acc[4]); acc[5] = fmaf(xc, w1.y, acc[5]);
        acc[6] = fmaf(xc, w1.z, acc[6]); acc[7] = fmaf(xc, w1.w, acc[7]);
    }
    if (r < 58) {
        float* dst = &g_Wpart[(ks * 58 + r) * NKPAD + ct * 32 + cg * 8];
        *(float4*)dst       = make_float4(acc[0], acc[1], acc[2], acc[3]);
        *(float4*)(dst + 4) = make_float4(acc[4], acc[5], acc[6], acc[7]);
    }
}

// ---------------------------------------------------------------------------
// Kernel B: reduce split-K partials, fold neighbor 3x3 terms AND the root
// (joint 0) subtraction directly into W' and b'. Pads cols [151,160) to 0.
// ---------------------------------------------------------------------------
__global__ void __launch_bounds__(NKPAD)
finalize_kernel(const float* __restrict__ b_shape, const float* __restrict__ b_cam,
                const float* __restrict__ b_phi,   const float* __restrict__ b_leaf,
                const float* __restrict__ init_shape, const float* __restrict__ init_cam,
                const float* __restrict__ reg_b)
{
    GDC_LAUNCH();   // let main launch + stage X while we run
    GDC_WAIT();     // everything below reads precompute's outputs

    int row = blockIdx.x;    // 0..57
    int col = threadIdx.x;   // 0..159
    float s = 0.f;
    #pragma unroll
    for (int p = 0; p < KSPLIT; p++) s += g_Wpart[(p * 58 + row) * NKPAD + col];

    bool isPose = (col >= 79 && col < NK);
    int t = 0, j = 0, o = 0;
    float s0 = 0.f;
    if (isPose) {
        t = col - 79; j = t / 3; o = t - 3 * j;
        #pragma unroll
        for (int p = 0; p < KSPLIT; p++) s0 += g_Wpart[(p * 58 + row) * NKPAD + 79 + o];
    }

    if (row < NC) {
        float w;
        if (col >= NK) {
            w = 0.f;
        } else if (!isPose) {
            w = s;
        } else {
            w = s - s0;
            int a1 = c_NB1[j], a2 = c_NB2[j];
            if (row >= a1 && row < a1 + 3) w += g_M1[j * 9 + (row - a1) * 3 + o];
            if (row >= a2 && row < a2 + 3) w += g_M2[j * 9 + (row - a2) * 3 + o];
            // subtract joint-0 neighbor scatter (NB1[0]=51, NB2[0]=54)
            if (row >= 51 && row < 54) w -= g_M1[(row - 51) * 3 + o];
            if (row >= 54 && row < 57) w -= g_M2[(row - 54) * 3 + o];
        }
        g_W[row * NKPAD + col] = w;
    } else {
        float bv;
        if      (col >= NK) bv = 0.f;
        else if (col < 10)  bv = s + b_shape[col] + init_shape[col];
        else if (col < 13)  bv = s + b_cam[col - 10] + init_cam[col - 10];
        else if (col < 59)  bv = s + b_phi[col - 13];
        else if (col < 79)  bv = s + b_leaf[col - 59];
        else {
            float bt = s  + reg_b[t] + g_bp1[t] + g_bp2[t];
            float b0 = s0 + reg_b[o] + g_bp1[o] + g_bp2[o];
            bv = bt - b0;
        }
        g_b[col] = bv;
    }
}

// ---------------------------------------------------------------------------
// Kernel C: main — out(B,151) = x(B,57) @ W' + b'. Scalar FFMA.
// Block = 128 threads covering 64 rows x 16 cols; results staged in smem,
// stored as 16-float contiguous runs (coalesced). grid = (B/64, 10 slices).
// X staging (input-only) runs BEFORE griddepcontrol.wait -> overlaps finalize.
// ---------------------------------------------------------------------------
__global__ void __launch_bounds__(TPB)
main_kernel(const float* __restrict__ joints, float* __restrict__ out, int B)
{
    __shared__ __align__(16) float  Xs[RPB * NC];     // 64*57*4 = 14592 B
    __shared__ __align__(16) float4 Ws4[NC][CPB / 4]; // 57*16*4 = 3648 B
    __shared__ float bias_s[CPB];
    __shared__ __align__(16) float  Os[RPB * CPB];    // 64*16*4 = 4096 B

    const int tid = threadIdx.x;
    const int rb  = blockIdx.x * RPB;
    const int k0  = blockIdx.y * CPB;

    // output section offsets (pose first, per output layout)
    const int CAM_OFF   = B * 72;
    const int PHI_OFF   = CAM_OFF + B * 3;
    const int LEAF_OFF  = PHI_OFF + B * 46;
    const int SHAPE_OFF = LEAF_OFF + B * 20;

    // ---- stage X (independent of upstream kernels -> before the wait) ----
    if (rb + RPB <= B) {
        const float4* jp = (const float4*)(joints + rb * NC);
        float4 xv[8];
        #pragma unroll
        for (int i = 0; i < 8; i++) {
            int idx = tid + TPB * i;
            if (idx < 912) xv[i] = jp[idx];
        }
        #pragma unroll
        for (int i = 0; i < 8; i++) {
            int idx = tid + TPB * i;
            if (idx < 912) ((float4*)Xs)[idx] = xv[i];
        }
    } else {
        int nr = B - rb;
        for (int idx = tid; idx < nr * NC; idx += TPB)
            Xs[idx] = joints[rb * NC + idx];
    }

    GDC_WAIT();     // finalize's g_W / g_b must be complete below

    // ---- stage W slice (batched): 57 rows x 4 float4 = 228 float4 ----
    {
        float4 wv[2];
        #pragma unroll
        for (int i = 0; i < 2; i++) {
            int idx = tid + TPB * i;
            if (idx < 228) {
                int r = idx >> 2, q = idx & 3;
                wv[i] = *(const float4*)(g_W + r * NKPAD + k0 + q * 4);
            }
        }
        #pragma unroll
        for (int i = 0; i < 2; i++) {
            int idx = tid + TPB * i;
            if (idx < 228) {
                int r = idx >> 2, q = idx & 3;
                Ws4[r][q] = wv[i];
            }
        }
    }
    if (tid < CPB) bias_s[tid] = g_b[k0 + tid];
    __syncthreads();

    const int ty = tid >> 1;          // row within tile (0..63)
    const int tx = tid & 1;           // column half (0/1)

    {
        float4 a0 = make_float4(bias_s[tx * 8 + 0], bias_s[tx * 8 + 1],
                                bias_s[tx * 8 + 2], bias_s[tx * 8 + 3]);
        float4 a1 = make_float4(bias_s[tx * 8 + 4], bias_s[tx * 8 + 5],
                                bias_s[tx * 8 + 6], bias_s[tx * 8 + 7]);

        const float* xrow = &Xs[ty * NC];
        #pragma unroll
        for (int c = 0; c < NC; c++) {
            float  xc = xrow[c];
            float4 w0 = Ws4[c][tx * 2];
            float4 w1 = Ws4[c][tx * 2 + 1];
            a0.x = fmaf(xc, w0.x, a0.x); a0.y = fmaf(xc, w0.y, a0.y);
            a0.z = fmaf(xc, w0.z, a0.z); a0.w = fmaf(xc, w0.w, a0.w);
            a1.x = fmaf(xc, w1.x, a1.x); a1.y = fmaf(xc, w1.y, a1.y);
            a1.z = fmaf(xc, w1.z, a1.z); a1.w = fmaf(xc, w1.w, a1.w);
        }

        float4* op = (float4*)&Os[ty * CPB + tx * 8];
        op[0] = a0;
        op[1] = a1;
    }
    __syncthreads();

    // ---- coalesced store: warp covers 2 rows x 16 consecutive k ----
    #pragma unroll
    for (int i = 0; i < 8; i++) {
        int idx = tid + TPB * i;          // 0..1023
        int e = idx & (CPB - 1);
        int r = idx >> 4;
        int k = k0 + e;
        int b = rb + r;
        if (k < NK && b < B) {
            float val = Os[idx];
            if      (k < 10) out[SHAPE_OFF + b * 10 + k]        = val;
            else if (k < 13) out[CAM_OFF   + b * 3  + (k - 10)] = val;
            else if (k < 59) out[PHI_OFF   + b * 46 + (k - 13)] = val;
            else if (k < 79) out[LEAF_OFF  + b * 20 + (k - 59)] = val;
            else             out[b * 72 + (k - 79)]             = val;
        }
    }
}

// ---------------------------------------------------------------------------
extern "C" void kernel_launch(void* const* d_in, const int* in_sizes, int n_in,
                              void* d_out, int out_size)
{
    const float* joints     = (const float*)d_in[0];
    const float* W_enc      = (const float*)d_in[1];
    const float* b_enc      = (const float*)d_in[2];
    const float* W_shape    = (const float*)d_in[3];
    const float* b_shape    = (const float*)d_in[4];
    const float* W_cam      = (const float*)d_in[5];
    const float* b_cam      = (const float*)d_in[6];
    const float* W_phi      = (const float*)d_in[7];
    const float* b_phi      = (const float*)d_in[8];
    const float* W_leaf     = (const float*)d_in[9];
    const float* b_leaf     = (const float*)d_in[10];
    const float* init_shape = (const float*)d_in[11];
    const float* init_cam   = (const float*)d_in[12];
    const float* L1_w       = (const float*)d_in[13];
    const float* L1_b       = (const float*)d_in[14];
    const float* L2_w       = (const float*)d_in[15];
    const float* L2_b       = (const float*)d_in[16];
    const float* Rf         = (const float*)d_in[17];
    const float* R1         = (const float*)d_in[18];
    const float* R2         = (const float*)d_in[19];
    const float* reg_b      = (const float*)d_in[20];

    int B = in_sizes[0] / NC;
    float* outf = (float*)d_out;

    // Kernel 1: normal launch
    precompute_kernel<<<5 * KSPLIT + 48, 256>>>(W_enc, b_enc, W_shape, W_cam, W_phi, W_leaf, Rf,
                                                L1_w, L1_b, L2_w, L2_b, R1, R2);

    // Kernels 2+3: programmatic dependent launch (upstream triggers at entry;
    // downstream's griddepcontrol.wait enforces full upstream completion).
    cudaLaunchAttribute pssAttr[1];
    pssAttr[0].id = cudaLaunchAttributeProgrammaticStreamSerialization;
    pssAttr[0].val.programmaticStreamSerializationAllowed = 1;

    {
        cudaLaunchConfig_t cfg = {};
        cfg.gridDim  = dim3(58);
        cfg.blockDim = dim3(NKPAD);
        cfg.attrs    = pssAttr;
        cfg.numAttrs = 1;
        cudaLaunchKernelEx(&cfg, finalize_kernel,
                           b_shape, b_cam, b_phi, b_leaf, init_shape, init_cam, reg_b);
    }
    {
        cudaLaunchConfig_t cfg = {};
        cfg.gridDim  = dim3((B + RPB - 1) / RPB, NSLICES);
        cfg.blockDim = dim3(TPB);
        cfg.attrs    = pssAttr;
        cfg.numAttrs = 1;
        cudaLaunchKernelEx(&cfg, main_kernel, joints, outf, B);
    }
}